// round 16
// baseline (speedup 1.0000x reference)
#include <cuda_runtime.h>

// out[b, t, f] = (t == (int)((1.0f - x[b,f]) * 100.0f)) ? 1.0f : 0.0f
// B=2048, T=100, F=1024. Output 839 MB -> pure HBM-store-bound.
// R16: disambiguation probe - 4KB block footprint while KEEPING the
//      2-stores-per-thread rule: 128 threads, each thread owns one f4 in
//      half the row and 2 t-steps? No - threads must stay coalesced across
//      a full 4KB t-row. Layout: 128 threads cover half a t-row (2KB) and
//      each thread stores that half-row at t0 and t0+1 -> block footprint
//      2 rows x 2KB = 4KB. blockIdx.x: 2 half-row chunks x 50 t-chunks
//      (fastest), blockIdx.y: batch. Stores remain fully coalesced
//      (warp = contiguous 512B).

#define B 2048
#define T 100
#define TCHUNK 2
#define NCHUNK (T / TCHUNK)   // 50
#define F 1024
#define F4 (F / 4)            // 256
#define HALF 128              // threads per block; half a t-row of float4

__global__ __launch_bounds__(128, 16)
void spike_latency_kernel(const float4* __restrict__ x, float4* __restrict__ out) {
    int bx   = blockIdx.x;               // 0 .. 2*NCHUNK-1, t fastest within half
    int half = bx >= NCHUNK;             // which half of the feature row
    int t0   = (half ? bx - NCHUNK : bx) * TCHUNK;
    int b    = blockIdx.y;
    int f4   = half * HALF + threadIdx.x; // 0..127 or 128..255

    float4 xv = __ldg(x + (size_t)b * F4 + f4);
    int s0 = (int)((1.0f - xv.x) * 100.0f);
    int s1 = (int)((1.0f - xv.y) * 100.0f);
    int s2 = (int)((1.0f - xv.z) * 100.0f);
    int s3 = (int)((1.0f - xv.w) * 100.0f);

    float4* po = out + (size_t)b * (T * F4) + (size_t)t0 * F4 + f4;

#pragma unroll
    for (int i = 0; i < TCHUNK; i++) {
        int t = t0 + i;
        float4 v;
        v.x = (t == s0) ? 1.0f : 0.0f;
        v.y = (t == s1) ? 1.0f : 0.0f;
        v.z = (t == s2) ? 1.0f : 0.0f;
        v.w = (t == s3) ? 1.0f : 0.0f;
        __stcs(po + (size_t)i * F4, v);   // evict-first streaming store
    }
}

extern "C" void kernel_launch(void* const* d_in, const int* in_sizes, int n_in,
                              void* d_out, int out_size) {
    const float4* x = (const float4*)d_in[0];
    float4* out = (float4*)d_out;
    dim3 grid(2 * NCHUNK, B);            // (100, 2048) = 204800 blocks
    spike_latency_kernel<<<grid, 128>>>(x, out);
}

// round 17
// speedup vs baseline: 1.5038x; 1.5038x over previous
#include <cuda_runtime.h>

// out[b, t, f] = (t == (int)((1.0f - x[b,f]) * 100.0f)) ? 1.0f : 0.0f
// B=2048, T=100, F=1024. Output 839 MB -> pure HBM-store-bound.
// FINAL (reproduced 3x at 113.0-113.15 us = 7.43 TB/s = 93% of HBM spec):
//   - 102400 blocks x 256 threads, TCHUNK=2: each thread does 1 L2-hit
//     x-load then 2 independent STG.128.cs. Measured optimum of the full
//     shape grid:
//       blocks x thr: 51.2kx256:114.6 / 102.4kx256:113.0 /
//                     204.8kx256:127.0 / 204.8kx128:170.5
//       stores/thread: 2:113.0 / 1:144.4 (load latency exposed)
//       width: 128b:113.0 / 256b(v8):131.6
//       policy: .cs:113.0 ~= default:120.8(at coarse grain) / .wt:143.9
//   - 2D grid with t-chunk fastest-varying: dense ~24MB concurrent write
//     footprint (DRAM locality win) + L2-resident x reuse, no int division.
// Residual ~7% DRAM idle is write turnaround/refresh - not SM-reachable.

#define B 2048
#define T 100
#define TCHUNK 2
#define NCHUNK (T / TCHUNK)   // 50
#define F 1024
#define F4 (F / 4)            // 256

__global__ __launch_bounds__(256, 8)
void spike_latency_kernel(const float4* __restrict__ x, float4* __restrict__ out) {
    int t0 = blockIdx.x * TCHUNK;        // t-chunk: fastest-varying -> dense wave
    int b  = blockIdx.y;                 // batch row
    int f4 = threadIdx.x;                // 0 .. 255

    float4 xv = __ldg(x + (size_t)b * F4 + f4);
    int s0 = (int)((1.0f - xv.x) * 100.0f);
    int s1 = (int)((1.0f - xv.y) * 100.0f);
    int s2 = (int)((1.0f - xv.z) * 100.0f);
    int s3 = (int)((1.0f - xv.w) * 100.0f);

    float4* po = out + (size_t)b * (T * F4) + (size_t)t0 * F4 + f4;

#pragma unroll
    for (int i = 0; i < TCHUNK; i++) {
        int t = t0 + i;
        float4 v;
        v.x = (t == s0) ? 1.0f : 0.0f;
        v.y = (t == s1) ? 1.0f : 0.0f;
        v.z = (t == s2) ? 1.0f : 0.0f;
        v.w = (t == s3) ? 1.0f : 0.0f;
        __stcs(po + (size_t)i * F4, v);   // evict-first streaming store
    }
}

extern "C" void kernel_launch(void* const* d_in, const int* in_sizes, int n_in,
                              void* d_out, int out_size) {
    const float4* x = (const float4*)d_in[0];
    float4* out = (float4*)d_out;
    dim3 grid(NCHUNK, B);                // (50, 2048) = 102400 blocks
    spike_latency_kernel<<<grid, 256>>>(x, out);
}